// round 15
// baseline (speedup 1.0000x reference)
#include <cuda_runtime.h>
#include <math.h>
#include <float.h>

// ---------------- problem constants ----------------
// x: (B=16, C=1024, H=64, W=64) fp32. out: (16,1024,1,1) fp32.
// 14 distinct regions (full region weighted x2):
//  r0:  (0,0,64)
//  r1..r4:  wl=42 at (i,j) in {0,22}x{0,22}  (i-major)
//  r5..r13: wl=32 at (i,j) in {0,16,32}^2    (i-major)
#define B 16
#define C 1024
#define HW 64
#define NPIX 4096          // 64*64
#define NGRP 64            // channel groups (16 channels each)
#define NREG 14

// Elementary segments (rows and cols use the same decomposition):
// E0[0,16) E1[16,22) E2[22,32) E3[32,42) E4[42,48) E5[48,64)
// In "pair" units (2 rows/cols): E0[0,8) E1[8,11) E2[11,16) E3[16,21) E4[21,24) E5[24,32)
__constant__ int c_elemStart[7] = {0, 8, 11, 16, 21, 24, 32};

// Row segment -> up to 2 warp-part codes (code = warp*2 + part), -1 = none.
// Warp w owns rowpairs [4w, 4w+4). Only w2 (boundary pair 11) and w5 (pair 21)
// straddle a segment: w2 partA=pairs{8,9,10} partB={11}; w5 partA={20} partB={21,22,23}.
__constant__ int c_rsPart[6][2] = {
    {0, 2},    // R0 rows[0,16)  = w0 all, w1 all
    {4, -1},   // R1 rows[16,22) = w2 partA
    {5, 6},    // R2 rows[22,32) = w2 partB, w3 all
    {8, 10},   // R3 rows[32,42) = w4 all,  w5 partA
    {11, -1},  // R4 rows[42,48) = w5 partB
    {12, 14}   // R5 rows[48,64) = w6 all,  w7 all
};

// Interval -> elementary bitmask:
// [0,64)=63  [0,42)=15  [22,64)=60  [0,32)=7  [16,48)=30  [32,64)=56
__constant__ int c_rowmask[NREG] = {63, 15,15,60,60, 7,7,7, 30,30,30, 56,56,56};
__constant__ int c_colmask[NREG] = {63, 15,60,15,60, 7,30,56, 7,30,56, 7,30,56};
__constant__ float c_area[NREG] = {4096.f, 1764.f,1764.f,1764.f,1764.f,
                                   1024.f,1024.f,1024.f,1024.f,1024.f,1024.f,1024.f,1024.f,1024.f};

// ---------------- device scratch (no allocations allowed) ----------------
__device__ float g_spart[NGRP * B * NPIX];   // 16.8 MB partial channel sums (L2-resident)
__device__ float g_s[B * NPIX];              // channel sums
__device__ float g_btot[128];                // per-block totals of s
__device__ float g_vt[NREG * B * C];         // region maxes
__device__ float g_scale[NREG * B];          // per (region,batch) final scale
__device__ int   g_cnt[NREG];                // tt counts per region

// ================= kernel A: coalesced pass, NO barriers in main loop =================
// grid (64 groups, 16 batches), block = 256 threads = 8 warps.
// Warp w owns pixel rows [8w, 8w+8) (128 consecutive float4s per channel).
// All per-channel max reduction is warp-local (shuffle + registers); each warp
// writes its own private smem slice, so the 16-channel loop has ZERO barriers.
// x loads use __ldcs (evict-first) so the 256MB stream does not evict the
// 16.8MB spart working set from L2 before kB1 re-reads it.
__global__ __launch_bounds__(256) void kA(const float* __restrict__ x) {
    const int g = blockIdx.x;          // channel group 0..63
    const int b = blockIdx.y;          // batch
    const int tid = threadIdx.x;
    const int w = tid >> 5;            // warp 0..7 -> rows [8w, 8w+8)
    const int l = tid & 31;            // lane
    const int m = l & 15;              // col-quad: cols [4m, 4m+3]

    // per (channel, warp, rowpart, colpair) maxes; each warp writes only its slice
    __shared__ float smP[16][8][2][32];       // 32 KB
    __shared__ float elemG[16][6][6];         // elementary 6x6 grid per channel

    // per-pixel partial sums over the 16 channels (float4 idx = 128w + 32i + l)
    float4 sum0 = make_float4(0.f,0.f,0.f,0.f), sum1 = sum0, sum2 = sum0, sum3 = sum0;

    const float4* __restrict__ xbase = reinterpret_cast<const float4*>(
        x + (((size_t)b * C + (size_t)g * 16) * NPIX)) + w * 128 + l;

#pragma unroll
    for (int ch = 0; ch < 16; ch++) {
        const float4* __restrict__ xr = xbase + (size_t)ch * (NPIX / 4);
        float4 v0 = __ldcs(xr);
        float4 v1 = __ldcs(xr + 32);
        float4 v2 = __ldcs(xr + 64);
        float4 v3 = __ldcs(xr + 96);

        sum0.x += v0.x; sum0.y += v0.y; sum0.z += v0.z; sum0.w += v0.w;
        sum1.x += v1.x; sum1.y += v1.y; sum1.z += v1.z; sum1.w += v1.w;
        sum2.x += v2.x; sum2.y += v2.y; sum2.z += v2.z; sum2.w += v2.w;
        sum3.x += v3.x; sum3.y += v3.y; sum3.z += v3.z; sum3.w += v3.w;

        // colpair maxes; iteration i covers rowpair 4w+i (row parity = l>=16)
        float mx[4][2];
        mx[0][0] = fmaxf(v0.x, v0.y); mx[0][1] = fmaxf(v0.z, v0.w);
        mx[1][0] = fmaxf(v1.x, v1.y); mx[1][1] = fmaxf(v1.z, v1.w);
        mx[2][0] = fmaxf(v2.x, v2.y); mx[2][1] = fmaxf(v2.z, v2.w);
        mx[3][0] = fmaxf(v3.x, v3.y); mx[3][1] = fmaxf(v3.z, v3.w);

        // merge the two row parities (rows 2i / 2i+1 always share a row segment)
#pragma unroll
        for (int i = 0; i < 4; i++) {
            mx[i][0] = fmaxf(mx[i][0], __shfl_xor_sync(0xffffffffu, mx[i][0], 16));
            mx[i][1] = fmaxf(mx[i][1], __shfl_xor_sync(0xffffffffu, mx[i][1], 16));
        }

        // reduce 4 rowpairs -> <=2 row-parts (uniform branch on warp id)
        float pA[2], pB[2];
#pragma unroll
        for (int p = 0; p < 2; p++) {
            if (w == 2) {          // rowpairs 8,9,10 | 11   (boundary row 22)
                pA[p] = fmaxf(fmaxf(mx[0][p], mx[1][p]), mx[2][p]);
                pB[p] = mx[3][p];
            } else if (w == 5) {   // rowpair 20 | 21,22,23  (boundary row 42)
                pA[p] = mx[0][p];
                pB[p] = fmaxf(fmaxf(mx[1][p], mx[2][p]), mx[3][p]);
            } else {
                pA[p] = fmaxf(fmaxf(mx[0][p], mx[1][p]), fmaxf(mx[2][p], mx[3][p]));
                pB[p] = -INFINITY;
            }
        }

        // lanes 0..15 publish (colpairs 2m, 2m+1) as one float2 each
        if (l < 16) {
            *reinterpret_cast<float2*>(&smP[ch][w][0][2 * m]) = make_float2(pA[0], pA[1]);
            *reinterpret_cast<float2*>(&smP[ch][w][1][2 * m]) = make_float2(pB[0], pB[1]);
        }
    }

    // write partial channel sums (coalesced STG.128; normal policy -> stays in L2)
    float4* sp = reinterpret_cast<float4*>(&g_spart[((size_t)(g * B + b)) * NPIX]) + w * 128 + l;
    sp[0]  = sum0;
    sp[32] = sum1;
    sp[64] = sum2;
    sp[96] = sum3;

    __syncthreads();   // the ONLY barrier before the final reduction

    // phase 2a: 576 jobs = 16 channels x 36 elementary cells
    for (int j = tid; j < 16 * 36; j += 256) {
        const int ch = j / 36;
        const int rc = j % 36;
        const int re = rc / 6, ce = rc % 6;
        const int c0 = c_elemStart[ce], c1 = c_elemStart[ce + 1];
        float mm = -INFINITY;
        const int p0 = c_rsPart[re][0];
        const float* s0 = &smP[ch][p0 >> 1][p0 & 1][0];
        for (int cp = c0; cp < c1; cp++) mm = fmaxf(mm, s0[cp]);
        const int p1 = c_rsPart[re][1];
        if (p1 >= 0) {
            const float* s1 = &smP[ch][p1 >> 1][p1 & 1][0];
            for (int cp = c0; cp < c1; cp++) mm = fmaxf(mm, s1[cp]);
        }
        elemG[ch][re][ce] = mm;
    }
    __syncthreads();

    // phase 2b: 224 jobs = 16 channels x 14 regions -> region maxes
    if (tid < 16 * NREG) {
        const int ch = tid / NREG;
        const int r  = tid % NREG;
        const int rm = c_rowmask[r], cm = c_colmask[r];
        float mm = -INFINITY;
#pragma unroll
        for (int re = 0; re < 6; re++) {
            if (!(rm & (1 << re))) continue;
#pragma unroll
            for (int ce = 0; ce < 6; ce++) {
                if (!(cm & (1 << ce))) continue;
                mm = fmaxf(mm, elemG[ch][re][ce]);
            }
        }
        g_vt[(r * B + b) * C + g * 16 + ch] = mm;
    }
}

// ================= kernel B1: reduce partials -> s, block totals =================
// 128 blocks x 512 threads (more SM coverage). spart is mostly L2-resident.
__global__ __launch_bounds__(512) void kB1() {
    const int tid = threadIdx.x;
    const int gp = blockIdx.x * 512 + tid;   // global pixel over (b, p)
    float sv = 0.f;
#pragma unroll 8
    for (int g2 = 0; g2 < NGRP; g2++) sv += g_spart[(size_t)g2 * (B * NPIX) + gp];
    g_s[gp] = sv;

    __shared__ float red[512];
    red[tid] = sv;
    __syncthreads();
    for (int off = 256; off > 0; off >>= 1) {
        if (tid < off) red[tid] += red[tid + off];
        __syncthreads();
    }
    if (tid == 0) g_btot[blockIdx.x] = red[0];
    if (blockIdx.x == 0 && tid < NREG) g_cnt[tid] = 0;  // zero counters for kB2
}

// ================= kernel B2: mean + per-region tt counts =================
__global__ __launch_bounds__(1024) void kB2() {
    __shared__ float s_mean;
    const int tid = threadIdx.x;
    if (tid == 0) {
        float t = 0.f;
        for (int i = 0; i < 128; i++) t += g_btot[i];
        s_mean = t / (float)(B * NPIX);
    }
    __syncthreads();

    const int gp = blockIdx.x * 1024 + tid;
    const float sv = g_s[gp];
    const bool tt = (sv - s_mean) > 0.f;
    const int p = gp & (NPIX - 1);
    const int h = p >> 6;
    const int w = p & 63;

    const bool h42a = h < 42, h42b = h >= 22, w42a = w < 42, w42b = w >= 22;
    const bool h32a = h < 32, h32b = (h >= 16 && h < 48), h32c = h >= 32;
    const bool w32a = w < 32, w32b = (w >= 16 && w < 48), w32c = w >= 32;

    bool mem[NREG];
    mem[0]  = true;
    mem[1]  = h42a && w42a;  mem[2]  = h42a && w42b;
    mem[3]  = h42b && w42a;  mem[4]  = h42b && w42b;
    mem[5]  = h32a && w32a;  mem[6]  = h32a && w32b;  mem[7]  = h32a && w32c;
    mem[8]  = h32b && w32a;  mem[9]  = h32b && w32b;  mem[10] = h32b && w32c;
    mem[11] = h32c && w32a;  mem[12] = h32c && w32b;  mem[13] = h32c && w32c;

    unsigned bal[NREG];
#pragma unroll
    for (int r = 0; r < NREG; r++)
        bal[r] = __ballot_sync(0xffffffffu, tt && mem[r]);
    const int lane = tid & 31;
    if (lane < NREG) atomicAdd(&g_cnt[lane], __popc(bal[lane]));  // int atomics: deterministic
}

// ================= kernel C1: per (region,batch) norm -> scale =================
// grid = 224 blocks (one per r,b), 128 threads. Tiny reduce, full-chip spread.
__global__ __launch_bounds__(128) void kC1() {
    const int rb = blockIdx.x;       // rb = r * B + b
    const int r = rb / B;
    const int tid = threadIdx.x;
    const int lane = tid & 31;
    const int warp = tid >> 5;

    const float* vt = &g_vt[rb * C];
    float ss = 0.f;
#pragma unroll
    for (int i = 0; i < 8; i++) {
        float v = vt[tid + i * 128];
        ss += v * v;
    }
#pragma unroll
    for (int o = 16; o > 0; o >>= 1)
        ss += __shfl_xor_sync(0xffffffffu, ss, o);

    __shared__ float wsum[4];
    if (lane == 0) wsum[warp] = ss;
    __syncthreads();
    if (tid == 0) {
        const float nrm = sqrtf(wsum[0] + wsum[1] + wsum[2] + wsum[3]);
        float wgt = (float)g_cnt[r] / c_area[r];
        if (wgt <= (1.0f / 3.0f)) wgt = 0.f;
        if (r == 0) wgt *= 2.0f;            // full region appears twice
        g_scale[rb] = wgt / (nrm + 1e-6f);
    }
}

// ================= kernel C2: final combine =================
// grid 64 x 256: each thread one (b,c); 14 coalesced loads + broadcast scales.
__global__ __launch_bounds__(256) void kC2(float* __restrict__ out) {
    const int b = blockIdx.x >> 2;                 // 4 blocks per batch
    const int c = (blockIdx.x & 3) * 256 + threadIdx.x;

    __shared__ float sc[NREG];
    if (threadIdx.x < NREG) sc[threadIdx.x] = g_scale[threadIdx.x * B + b];
    __syncthreads();

    float o = 0.f;
#pragma unroll
    for (int r = 0; r < NREG; r++)
        o += g_vt[(r * B + b) * C + c] * sc[r];
    out[b * C + c] = o;
}

// ================= launch =================
extern "C" void kernel_launch(void* const* d_in, const int* in_sizes, int n_in,
                              void* d_out, int out_size) {
    const float* x = (const float*)d_in[0];
    float* out = (float*)d_out;
    kA<<<dim3(NGRP, B), 256>>>(x);
    kB1<<<128, 512>>>();
    kB2<<<64, 1024>>>();
    kC1<<<NREG * B, 128>>>();
    kC2<<<64, 256>>>(out);
}

// round 16
// speedup vs baseline: 1.1130x; 1.1130x over previous
#include <cuda_runtime.h>
#include <math.h>
#include <float.h>

// ---------------- problem constants ----------------
// x: (B=16, C=1024, H=64, W=64) fp32. out: (16,1024,1,1) fp32.
// 14 distinct regions (full region weighted x2):
//  r0:  (0,0,64)
//  r1..r4:  wl=42 at (i,j) in {0,22}x{0,22}  (i-major)
//  r5..r13: wl=32 at (i,j) in {0,16,32}^2    (i-major)
#define B 16
#define C 1024
#define HW 64
#define NPIX 4096          // 64*64
#define NGRP 32            // channel groups (32 channels each)
#define NREG 14
#define FXSCALE 16777216.0f   // 2^24 fixed-point scale for channel sums

// Elementary segments (rows and cols use the same decomposition):
// E0[0,16) E1[16,22) E2[22,32) E3[32,42) E4[42,48) E5[48,64)
// In "pair" units (2 rows/cols): E0[0,8) E1[8,11) E2[11,16) E3[16,21) E4[21,24) E5[24,32)
__constant__ int c_elemStart[7] = {0, 8, 11, 16, 21, 24, 32};

// Row segment -> up to 2 warp-part codes (code = warp*2 + part), -1 = none.
// Warp w owns rowpairs [4w, 4w+4). Only w2 (boundary pair 11) and w5 (pair 21)
// straddle a segment: w2 partA=pairs{8,9,10} partB={11}; w5 partA={20} partB={21,22,23}.
__constant__ int c_rsPart[6][2] = {
    {0, 2},    // R0 rows[0,16)  = w0 all, w1 all
    {4, -1},   // R1 rows[16,22) = w2 partA
    {5, 6},    // R2 rows[22,32) = w2 partB, w3 all
    {8, 10},   // R3 rows[32,42) = w4 all,  w5 partA
    {11, -1},  // R4 rows[42,48) = w5 partB
    {12, 14}   // R5 rows[48,64) = w6 all,  w7 all
};

// Interval -> elementary bitmask:
// [0,64)=63  [0,42)=15  [22,64)=60  [0,32)=7  [16,48)=30  [32,64)=56
__constant__ int c_rowmask[NREG] = {63, 15,15,60,60, 7,7,7, 30,30,30, 56,56,56};
__constant__ int c_colmask[NREG] = {63, 15,60,15,60, 7,30,56, 7,30,56, 7,30,56};
__constant__ float c_area[NREG] = {4096.f, 1764.f,1764.f,1764.f,1764.f,
                                   1024.f,1024.f,1024.f,1024.f,1024.f,1024.f,1024.f,1024.f,1024.f};

// ---------------- device scratch (no allocations allowed) ----------------
__device__ unsigned long long g_s_fx[B * NPIX];  // fixed-point channel sums (2^24)
__device__ unsigned long long g_tot;             // total of all s_fx (for mean)
__device__ float g_vt[NREG * B * C];             // region maxes
__device__ float g_scale[NREG * B];              // per (region,batch) final scale
__device__ int   g_cnt[NREG];                    // tt counts per region

// ================= kernel Z: zero accumulators =================
__global__ __launch_bounds__(256) void kZ() {
    const int i = blockIdx.x * 256 + threadIdx.x;
    g_s_fx[i] = 0ull;
    if (i == 0) g_tot = 0ull;
    if (i < NREG) g_cnt[i] = 0;
}

// ================= kernel A: coalesced pass, barrier-free inner loops =================
// grid (32 groups, 16 batches) = 512 blocks x 256 threads (8 warps).
// Warp w owns pixel rows [8w, 8w+8) (128 consecutive float4s per channel).
// 32 channels per block, processed as two 16-channel halves; within a half the
// loop has ZERO barriers (warp-local shuffles + private smem slices); one
// barrier pair between halves reuses smP. Channel sums are accumulated in
// registers across all 32 channels, quantized to int64 fixed point, and
// atomically added (exact integer math -> deterministic) to g_s_fx / g_tot.
__global__ __launch_bounds__(256) void kA(const float* __restrict__ x) {
    const int g = blockIdx.x;          // channel group 0..31 (32 channels each)
    const int b = blockIdx.y;          // batch
    const int tid = threadIdx.x;
    const int w = tid >> 5;            // warp 0..7 -> rows [8w, 8w+8)
    const int l = tid & 31;            // lane
    const int m = l & 15;              // col-quad: cols [4m, 4m+3]

    __shared__ float smP[16][8][2][32];       // 32 KB, reused per half
    __shared__ float elemG[32][6][6];         // elementary 6x6 grid per channel

    // per-pixel partial sums over the 32 channels (float4 idx = 128w + 32i + l)
    float4 sum0 = make_float4(0.f,0.f,0.f,0.f), sum1 = sum0, sum2 = sum0, sum3 = sum0;

    const float4* __restrict__ xbase = reinterpret_cast<const float4*>(
        x + (((size_t)b * C + (size_t)g * 32) * NPIX)) + w * 128 + l;

#pragma unroll
    for (int half = 0; half < 2; half++) {
#pragma unroll
        for (int ch = 0; ch < 16; ch++) {
            const float4* __restrict__ xr = xbase + (size_t)(half * 16 + ch) * (NPIX / 4);
            float4 v0 = __ldcs(xr);
            float4 v1 = __ldcs(xr + 32);
            float4 v2 = __ldcs(xr + 64);
            float4 v3 = __ldcs(xr + 96);

            sum0.x += v0.x; sum0.y += v0.y; sum0.z += v0.z; sum0.w += v0.w;
            sum1.x += v1.x; sum1.y += v1.y; sum1.z += v1.z; sum1.w += v1.w;
            sum2.x += v2.x; sum2.y += v2.y; sum2.z += v2.z; sum2.w += v2.w;
            sum3.x += v3.x; sum3.y += v3.y; sum3.z += v3.z; sum3.w += v3.w;

            // colpair maxes; iteration i covers rowpair 4w+i (row parity = l>=16)
            float mx[4][2];
            mx[0][0] = fmaxf(v0.x, v0.y); mx[0][1] = fmaxf(v0.z, v0.w);
            mx[1][0] = fmaxf(v1.x, v1.y); mx[1][1] = fmaxf(v1.z, v1.w);
            mx[2][0] = fmaxf(v2.x, v2.y); mx[2][1] = fmaxf(v2.z, v2.w);
            mx[3][0] = fmaxf(v3.x, v3.y); mx[3][1] = fmaxf(v3.z, v3.w);

            // merge the two row parities (rows 2i/2i+1 always share a row segment)
#pragma unroll
            for (int i = 0; i < 4; i++) {
                mx[i][0] = fmaxf(mx[i][0], __shfl_xor_sync(0xffffffffu, mx[i][0], 16));
                mx[i][1] = fmaxf(mx[i][1], __shfl_xor_sync(0xffffffffu, mx[i][1], 16));
            }

            // reduce 4 rowpairs -> <=2 row-parts (uniform branch on warp id)
            float pA[2], pB[2];
#pragma unroll
            for (int p = 0; p < 2; p++) {
                if (w == 2) {          // rowpairs 8,9,10 | 11   (boundary row 22)
                    pA[p] = fmaxf(fmaxf(mx[0][p], mx[1][p]), mx[2][p]);
                    pB[p] = mx[3][p];
                } else if (w == 5) {   // rowpair 20 | 21,22,23  (boundary row 42)
                    pA[p] = mx[0][p];
                    pB[p] = fmaxf(fmaxf(mx[1][p], mx[2][p]), mx[3][p]);
                } else {
                    pA[p] = fmaxf(fmaxf(mx[0][p], mx[1][p]), fmaxf(mx[2][p], mx[3][p]));
                    pB[p] = -INFINITY;
                }
            }

            // lanes 0..15 publish (colpairs 2m, 2m+1) as one float2 each
            if (l < 16) {
                *reinterpret_cast<float2*>(&smP[ch][w][0][2 * m]) = make_float2(pA[0], pA[1]);
                *reinterpret_cast<float2*>(&smP[ch][w][1][2 * m]) = make_float2(pB[0], pB[1]);
            }
        }
        __syncthreads();

        // phase 2a: 576 jobs = 16 channels x 36 elementary cells
        for (int j = tid; j < 16 * 36; j += 256) {
            const int ch = j / 36;
            const int rc = j % 36;
            const int re = rc / 6, ce = rc % 6;
            const int c0 = c_elemStart[ce], c1 = c_elemStart[ce + 1];
            float mm = -INFINITY;
            const int p0 = c_rsPart[re][0];
            const float* s0 = &smP[ch][p0 >> 1][p0 & 1][0];
            for (int cp = c0; cp < c1; cp++) mm = fmaxf(mm, s0[cp]);
            const int p1 = c_rsPart[re][1];
            if (p1 >= 0) {
                const float* s1 = &smP[ch][p1 >> 1][p1 & 1][0];
                for (int cp = c0; cp < c1; cp++) mm = fmaxf(mm, s1[cp]);
            }
            elemG[half * 16 + ch][re][ce] = mm;
        }
        __syncthreads();   // smP reused by next half
    }

    // ---- channel sums: quantize to 2^24 fixed point, atomic-add (exact) ----
    {
        const float* s0 = &sum0.x;
        const float* s1 = &sum1.x;
        const float* s2 = &sum2.x;
        const float* s3 = &sum3.x;
        long long fx[16];
#pragma unroll
        for (int c4 = 0; c4 < 4; c4++) {
            fx[c4]      = llrintf(s0[c4] * FXSCALE);
            fx[4 + c4]  = llrintf(s1[c4] * FXSCALE);
            fx[8 + c4]  = llrintf(s2[c4] * FXSCALE);
            fx[12 + c4] = llrintf(s3[c4] * FXSCALE);
        }
        const int pixbase = b * NPIX;
        long long mytot = 0;
#pragma unroll
        for (int i = 0; i < 4; i++) {
            const int f4idx = w * 128 + 32 * i + l;
#pragma unroll
            for (int c4 = 0; c4 < 4; c4++) {
                const long long v = fx[i * 4 + c4];
                mytot += v;
                atomicAdd(&g_s_fx[pixbase + f4idx * 4 + c4], (unsigned long long)v);
            }
        }
        // block-total -> single atomic (deterministic integer add)
        unsigned lo = (unsigned)(unsigned long long)mytot;
        unsigned hi = (unsigned)(((unsigned long long)mytot) >> 32);
        // 64-bit warp reduce via paired 32-bit shuffles
#pragma unroll
        for (int o = 16; o > 0; o >>= 1) {
            unsigned long long cur = ((unsigned long long)hi << 32) | lo;
            long long other;
            {
                long long c2 = (long long)cur;
                other = __shfl_xor_sync(0xffffffffu, c2, o);
            }
            long long s = (long long)cur + other;
            lo = (unsigned)(unsigned long long)s;
            hi = (unsigned)(((unsigned long long)s) >> 32);
        }
        __shared__ long long wtot[8];
        if (l == 0) wtot[w] = (long long)(((unsigned long long)hi << 32) | lo);
        __syncthreads();
        if (tid == 0) {
            long long t = 0;
#pragma unroll
            for (int i = 0; i < 8; i++) t += wtot[i];
            atomicAdd(&g_tot, (unsigned long long)t);
        }
    }

    // phase 2b: 448 jobs = 32 channels x 14 regions -> region maxes
    for (int j = tid; j < 32 * NREG; j += 256) {
        const int ch = j / NREG;
        const int r  = j % NREG;
        const int rm = c_rowmask[r], cm = c_colmask[r];
        float mm = -INFINITY;
#pragma unroll
        for (int re = 0; re < 6; re++) {
            if (!(rm & (1 << re))) continue;
#pragma unroll
            for (int ce = 0; ce < 6; ce++) {
                if (!(cm & (1 << ce))) continue;
                mm = fmaxf(mm, elemG[ch][re][ce]);
            }
        }
        g_vt[(r * B + b) * C + g * 32 + ch] = mm;
    }
}

// ================= kernel B2: tt counts via exact integer threshold =================
// tt = (s - mean) > 0  <=>  NPIXTOT * s_fx > tot_fx   (exact in int64)
__global__ __launch_bounds__(1024) void kB2() {
    const int tid = threadIdx.x;
    const int gp = blockIdx.x * 1024 + tid;   // global pixel over (b, p)
    const long long sfx = (long long)g_s_fx[gp];
    const long long tot = (long long)g_tot;
    const bool tt = (sfx * (long long)(B * NPIX)) > tot;

    const int p = gp & (NPIX - 1);
    const int h = p >> 6;
    const int w = p & 63;

    const bool h42a = h < 42, h42b = h >= 22, w42a = w < 42, w42b = w >= 22;
    const bool h32a = h < 32, h32b = (h >= 16 && h < 48), h32c = h >= 32;
    const bool w32a = w < 32, w32b = (w >= 16 && w < 48), w32c = w >= 32;

    bool mem[NREG];
    mem[0]  = true;
    mem[1]  = h42a && w42a;  mem[2]  = h42a && w42b;
    mem[3]  = h42b && w42a;  mem[4]  = h42b && w42b;
    mem[5]  = h32a && w32a;  mem[6]  = h32a && w32b;  mem[7]  = h32a && w32c;
    mem[8]  = h32b && w32a;  mem[9]  = h32b && w32b;  mem[10] = h32b && w32c;
    mem[11] = h32c && w32a;  mem[12] = h32c && w32b;  mem[13] = h32c && w32c;

    unsigned bal[NREG];
#pragma unroll
    for (int r = 0; r < NREG; r++)
        bal[r] = __ballot_sync(0xffffffffu, tt && mem[r]);
    const int lane = tid & 31;
    if (lane < NREG) atomicAdd(&g_cnt[lane], __popc(bal[lane]));  // int atomics: deterministic
}

// ================= kernel C1: per (region,batch) norm -> scale =================
__global__ __launch_bounds__(128) void kC1() {
    const int rb = blockIdx.x;       // rb = r * B + b
    const int r = rb / B;
    const int tid = threadIdx.x;
    const int lane = tid & 31;
    const int warp = tid >> 5;

    const float* vt = &g_vt[rb * C];
    float ss = 0.f;
#pragma unroll
    for (int i = 0; i < 8; i++) {
        float v = vt[tid + i * 128];
        ss += v * v;
    }
#pragma unroll
    for (int o = 16; o > 0; o >>= 1)
        ss += __shfl_xor_sync(0xffffffffu, ss, o);

    __shared__ float wsum[4];
    if (lane == 0) wsum[warp] = ss;
    __syncthreads();
    if (tid == 0) {
        const float nrm = sqrtf(wsum[0] + wsum[1] + wsum[2] + wsum[3]);
        float wgt = (float)g_cnt[r] / c_area[r];
        if (wgt <= (1.0f / 3.0f)) wgt = 0.f;
        if (r == 0) wgt *= 2.0f;            // full region appears twice
        g_scale[rb] = wgt / (nrm + 1e-6f);
    }
}

// ================= kernel C2: final combine =================
__global__ __launch_bounds__(256) void kC2(float* __restrict__ out) {
    const int b = blockIdx.x >> 2;                 // 4 blocks per batch
    const int c = (blockIdx.x & 3) * 256 + threadIdx.x;

    __shared__ float sc[NREG];
    if (threadIdx.x < NREG) sc[threadIdx.x] = g_scale[threadIdx.x * B + b];
    __syncthreads();

    float o = 0.f;
#pragma unroll
    for (int r = 0; r < NREG; r++)
        o += g_vt[(r * B + b) * C + c] * sc[r];
    out[b * C + c] = o;
}

// ================= launch =================
extern "C" void kernel_launch(void* const* d_in, const int* in_sizes, int n_in,
                              void* d_out, int out_size) {
    const float* x = (const float*)d_in[0];
    float* out = (float*)d_out;
    kZ<<<256, 256>>>();
    kA<<<dim3(NGRP, B), 256>>>(x);
    kB2<<<64, 1024>>>();
    kC1<<<NREG * B, 128>>>();
    kC2<<<64, 256>>>(out);
}